// round 14
// baseline (speedup 1.0000x reference)
#include <cuda_runtime.h>
#include <math_constants.h>
#include <cstdint>

#define LSEQ 2048
#define BATCH 8
#define NROWS (BATCH*LSEQ)
#define K2N 32
#define K1N 16
#define NG 32
#define HIN 20
#define DM 128
#define DH 32
#define KDIM 640   // NG*HIN
#define NKS 40     // KDIM/16
#define KPAIRS 320 // KDIM/2

// ---------------- device scratch (static, no allocation) ----------------
__device__ float4 g_cpack[NROWS];
__device__ int   g_idx2[NROWS*K2N];
// A pre-split: [row][kpair] = {bf16x2 hi, bf16x2 lo}, k' = g*20+h, kpair = k'/2
__device__ uint2 g_Apk[(size_t)NROWS*KPAIRS];
__device__ float g_satt[NROWS];
__device__ float g_catt[NROWS];
__device__ float g_beta[NROWS];
__device__ float g_nodef[NROWS*2];
__device__ uint4 g_Bfrag[NKS*16*32];
__device__ float g_Q[18*32*2];
__device__ float g_Q2[11*32*2];

// ---------------- helpers ----------------
__device__ __forceinline__ void cvt_split(float2 v, uint32_t& h, uint32_t& l) {
    uint32_t hh;
    asm("cvt.rn.bf16x2.f32 %0, %1, %2;" : "=r"(hh) : "f"(v.y), "f"(v.x));
    float hx = __uint_as_float(hh << 16);
    float hy = __uint_as_float(hh & 0xffff0000u);
    float lx = v.x - hx, ly = v.y - hy;
    uint32_t ll;
    asm("cvt.rn.bf16x2.f32 %0, %1, %2;" : "=r"(ll) : "f"(ly), "f"(lx));
    h = hh; l = ll;
}
__device__ __forceinline__ void hmma(float* d, uint32_t a0, uint32_t a1,
                                     uint32_t a2, uint32_t a3,
                                     uint32_t b0, uint32_t b1) {
    asm("mma.sync.aligned.m16n8k16.row.col.f32.bf16.bf16.f32 "
        "{%0,%1,%2,%3}, {%4,%5,%6,%7}, {%8,%9}, {%0,%1,%2,%3};"
        : "+f"(d[0]), "+f"(d[1]), "+f"(d[2]), "+f"(d[3])
        : "r"(a0), "r"(a1), "r"(a2), "r"(a3), "r"(b0), "r"(b1));
}
__device__ __forceinline__ void fma2(uint64_t& d, uint64_t a, uint64_t b) {
    asm("fma.rn.f32x2 %0, %1, %2, %0;" : "+l"(d) : "l"(a), "l"(b));
}
__device__ __forceinline__ uint64_t dup2(float x) {
    uint64_t r; uint32_t u = __float_as_uint(x);
    asm("mov.b64 %0, {%1, %1};" : "=l"(r) : "r"(u));
    return r;
}
__device__ __forceinline__ float2 unpk(uint64_t v) {
    float lo, hi;
    asm("mov.b64 {%0, %1}, %2;" : "=f"(lo), "=f"(hi) : "l"(v));
    return make_float2(lo, hi);
}
__device__ __forceinline__ float knn_dist(float cx2, float cy2, float cz2,
                                          float ciw, float4 cm) {
    float s = __fmaf_rn(cz2, cm.z, cm.w + ciw);
    s = __fmaf_rn(cy2, cm.y, s);
    s = __fmaf_rn(cx2, cm.x, s);
    return fmaxf(s, 0.f);
}

// ---------------- kernel 0: merged prep (pack | bprep | qprep | qprep2) -----
// B fragments use k' = opk row order directly.
__global__ void __launch_bounds__(256) prep_kernel(
    const float* __restrict__ frame, const float* __restrict__ opk,
    const float* __restrict__ gk1_centers, const float* __restrict__ gk1_prec,
    const float* __restrict__ gk2_centers, const float* __restrict__ gk2_prec)
{
    int bid = blockIdx.x, tid = threadIdx.x;
    if (bid < 64) {
        int i = bid * 256 + tid;
        const float* f = frame + (size_t)i * 12;
        float x = f[0], y = f[1], z = f[2];
        g_cpack[i] = make_float4(x, y, z, x*x + y*y + z*z);
    } else if (bid < 144) {
        int idx = (bid - 64) * 256 + tid;
        int lane = idx & 31, na = (idx >> 5) & 15, ks = idx >> 9;
        int g = lane >> 2, t = lane & 3;
        int n = na*8 + g;
        int kb = ks*16 + 2*t;
        float2 p0 = make_float2(opk[(kb  )*DM + n], opk[(kb+1)*DM + n]);
        float2 p1 = make_float2(opk[(kb+8)*DM + n], opk[(kb+9)*DM + n]);
        uint32_t h0,l0,h1,l1;
        cvt_split(p0, h0, l0);
        cvt_split(p1, h1, l1);
        g_Bfrag[idx] = make_uint4(h0, h1, l0, l1);
    } else if (bid == 144) {
        if (tid >= 32) return;
        int g = tid;
        float P[7][7], c[7];
        #pragma unroll
        for (int d = 0; d < 7; d++) {
            c[d] = gk1_centers[d*NG + g];
            #pragma unroll
            for (int k = 0; k < 7; k++) P[d][k] = gk1_prec[(d*7+k)*NG + g];
        }
        float A[7][7];
        #pragma unroll
        for (int d = 0; d < 7; d++)
            #pragma unroll
            for (int e = 0; e < 7; e++) {
                float s = 0.f;
                #pragma unroll
                for (int k = 0; k < 7; k++) s += P[d][k]*P[e][k];
                A[d][e] = s;
            }
        float coeff[36];
        #pragma unroll
        for (int d = 0; d < 7; d++) {
            float s = 0.f;
            #pragma unroll
            for (int e = 0; e < 7; e++) s += A[d][e]*c[e];
            coeff[d] = -2.f*s;
        }
        int i = 7;
        #pragma unroll
        for (int d = 0; d < 7; d++)
            #pragma unroll
            for (int e = 0; e < 7; e++)
                if (e >= d) coeff[i++] = A[d][e]*((d==e)?1.f:2.f);
        float cc = 0.f;
        #pragma unroll
        for (int d = 0; d < 7; d++)
            #pragma unroll
            for (int e = 0; e < 7; e++) cc += c[d]*A[d][e]*c[e];
        coeff[35] = cc;
        #pragma unroll
        for (int p = 0; p < 18; p++) {
            g_Q[(p*32+g)*2 + 0] = coeff[2*p];
            g_Q[(p*32+g)*2 + 1] = coeff[2*p+1];
        }
    } else {
        if (tid >= 32) return;
        int g = tid;
        float P[5][5], c[5];
        #pragma unroll
        for (int d = 0; d < 5; d++) {
            c[d] = gk2_centers[d*NG + g];
            #pragma unroll
            for (int k = 0; k < 5; k++) P[d][k] = gk2_prec[(d*5+k)*NG + g];
        }
        float A[5][5];
        #pragma unroll
        for (int d = 0; d < 5; d++)
            #pragma unroll
            for (int e = 0; e < 5; e++) {
                float s = 0.f;
                #pragma unroll
                for (int k = 0; k < 5; k++) s += P[d][k]*P[e][k];
                A[d][e] = s;
            }
        float coeff[22];
        #pragma unroll
        for (int d = 0; d < 5; d++) {
            float s = 0.f;
            #pragma unroll
            for (int e = 0; e < 5; e++) s += A[d][e]*c[e];
            coeff[d] = -2.f*s;
        }
        int i = 5;
        #pragma unroll
        for (int d = 0; d < 5; d++)
            #pragma unroll
            for (int e = 0; e < 5; e++)
                if (e >= d) coeff[i++] = A[d][e]*((d==e)?1.f:2.f);
        float cc = 0.f;
        #pragma unroll
        for (int d = 0; d < 5; d++)
            #pragma unroll
            for (int e = 0; e < 5; e++) cc += c[d]*A[d][e]*c[e];
        coeff[20] = cc;
        coeff[21] = 0.f;
        #pragma unroll
        for (int p = 0; p < 11; p++) {
            g_Q2[(p*32+g)*2 + 0] = -0.5f*coeff[2*p];
            g_Q2[(p*32+g)*2 + 1] = -0.5f*coeff[2*p+1];
        }
    }
}

// ---------------- kernel 1: 32-NN, bf16 d-cache + threshold + exact rank ----
__global__ void __launch_bounds__(256) knn_kernel()
{
    __shared__ uint32_t dc_s[8][32][32];
    __shared__ unsigned long long buf_s[8][64];
    __shared__ int idx_s[8][64];
    int warp = threadIdx.x >> 5, lane = threadIdx.x & 31;
    int row  = blockIdx.x * 8 + warp;
    int b = row >> 11, l = row & (LSEQ-1);
    const float4* cb = g_cpack + (size_t)b * LSEQ;
    float4 ci = cb[l];
    float cx2 = -2.f*ci.x, cy2 = -2.f*ci.y, cz2 = -2.f*ci.z, ciw = ci.w;

    float v0 = CUDART_INF_F, v1 = CUDART_INF_F, v2 = CUDART_INF_F, v3 = CUDART_INF_F;
    uint32_t* dc = &dc_s[warp][0][0];
    #pragma unroll 2
    for (int t2 = 0; t2 < 32; t2++) {
        float4 ca = cb[t2*64 + lane];
        float4 cbq = cb[t2*64 + 32 + lane];
        float d0 = knn_dist(cx2, cy2, cz2, ciw, ca);
        float d1 = knn_dist(cx2, cy2, cz2, ciw, cbq);
        float a0, a1, a2;
        a0 = fmaxf(v0, d0); v0 = fminf(v0, d0);
        a1 = fmaxf(v1, a0); v1 = fminf(v1, a0);
        a2 = fmaxf(v2, a1); v2 = fminf(v2, a1);
        v3 = fminf(v3, a2);
        a0 = fmaxf(v0, d1); v0 = fminf(v0, d1);
        a1 = fmaxf(v1, a0); v1 = fminf(v1, a0);
        a2 = fmaxf(v2, a1); v2 = fminf(v2, a1);
        v3 = fminf(v3, a2);
        uint32_t pair;
        asm("cvt.rn.bf16x2.f32 %0, %1, %2;" : "=r"(pair) : "f"(d1), "f"(d0));
        dc[t2*32 + lane] = pair;
    }

    float T = 0.f;
    for (int s = 0; s < K2N; s++) {
        unsigned mnb  = __reduce_min_sync(0xffffffffu, __float_as_uint(v0));
        unsigned ball = __ballot_sync(0xffffffffu, __float_as_uint(v0) == mnb);
        if (lane == __ffs(ball) - 1) { v0 = v1; v1 = v2; v2 = v3; v3 = CUDART_INF_F; }
        T = __uint_as_float(mnb);
    }
    uint32_t Tb;
    asm("cvt.rn.bf16x2.f32 %0, %1, %1;" : "=r"(Tb) : "f"(T));

    unsigned lmask = (1u << lane) - 1u;
    int* idxw = idx_s[warp];
    int base = 0;
    for (int t2 = 0; t2 < 32; t2++) {
        uint32_t pair = dc[t2*32 + lane];
        uint32_t mask = __vcmpleu2(pair, Tb);
        bool lo = (mask & 0x0000ffffu) != 0;
        bool hi = (mask & 0xffff0000u) != 0;
        unsigned bl = __ballot_sync(0xffffffffu, lo);
        if (lo) { int pos = base + __popc(bl & lmask); if (pos < 64) idxw[pos] = t2*64 + lane; }
        base += __popc(bl);
        unsigned bh = __ballot_sync(0xffffffffu, hi);
        if (hi) { int pos = base + __popc(bh & lmask); if (pos < 64) idxw[pos] = t2*64 + 32 + lane; }
        base += __popc(bh);
    }
    __syncwarp();

    int n = min(base, 64);
    unsigned long long* buf = buf_s[warp];
    for (int c = lane; c < n; c += 32) {
        int m = idxw[c];
        float4 cm = cb[m];
        float d = knn_dist(cx2, cy2, cz2, ciw, cm);
        buf[c] = ((unsigned long long)__float_as_uint(d) << 32) | (unsigned)m;
    }
    __syncwarp();
    for (int c = lane; c < n; c += 32) {
        unsigned long long x = buf[c];
        int r = 0;
        #pragma unroll 4
        for (int i = 0; i < n; i++) r += (buf[i] < x) ? 1 : 0;
        if (r < K2N) g_idx2[row*K2N + r] = (int)(x & 0xffffffffu);
    }
}

// ---------------- kernel 2: coords1 + gaussian dot + pre-split A store ------
__global__ void __launch_bounds__(256) stage1_kernel(
    const float* __restrict__ frame, const float* __restrict__ attr,
    const int* __restrict__ seq)
{
    __shared__ __align__(16) float attr_s[8][K1N][HIN];
    __shared__ __align__(16) float feat_s[8][K1N][36];
    int warp = threadIdx.x >> 5, lane = threadIdx.x & 31;
    int row  = blockIdx.x * 8 + warp;
    int b = row >> 11, l = row & (LSEQ-1);
    const float* fb = frame + (size_t)b * LSEQ * 12;

    if (lane < K1N) {
        int k = lane;
        int j = g_idx2[row*K2N + k];
        float fi[12];
        #pragma unroll
        for (int d = 0; d < 12; d++) fi[d] = fb[l*12+d];
        float cjx = fb[j*12+0], cjy = fb[j*12+1], cjz = fb[j*12+2];
        float zjx = fb[j*12+9], zjy = fb[j*12+10], zjz = fb[j*12+11];
        float dx = cjx - fi[0], dy = cjy - fi[1], dz = cjz - fi[2];
        float dist = sqrtf(dx*dx + dy*dy + dz*dz + 1e-12f);
        float x[7];
        x[0] = dx*fi[3] + dy*fi[4] + dz*fi[5];
        x[1] = dx*fi[6] + dy*fi[7] + dz*fi[8];
        x[2] = dx*fi[9] + dy*fi[10] + dz*fi[11];
        float seqi = (float)seq[b*LSEQ + l];
        float seqj = (float)seq[b*LSEQ + j];
        x[3] = fminf(fabsf(seqj - seqi), 8.0f);
        x[4] = fi[9]*zjx + fi[10]*zjy + fi[11]*zjz;
        x[5] = (dx*zjx + dy*zjy + dz*zjz) / dist;
        x[6] = (fi[9]*dx + fi[10]*dy + fi[11]*dz) / dist;
        float fv[36];
        #pragma unroll
        for (int d = 0; d < 7; d++) fv[d] = x[d];
        int i = 7;
        #pragma unroll
        for (int d = 0; d < 7; d++)
            #pragma unroll
            for (int e = 0; e < 7; e++)
                if (e >= d) fv[i++] = x[d]*x[e];
        fv[35] = 1.0f;
        float4* fd = (float4*)&feat_s[warp][k][0];
        #pragma unroll
        for (int q = 0; q < 9; q++)
            fd[q] = make_float4(fv[4*q], fv[4*q+1], fv[4*q+2], fv[4*q+3]);
    } else {
        int k = lane - K1N;
        int j = g_idx2[row*K2N + k];
        const float2* ap = (const float2*)(attr + ((size_t)b*LSEQ + j) * HIN);
        float2* dst = (float2*)&attr_s[warp][k][0];
        #pragma unroll
        for (int h = 0; h < HIN/2; h++) dst[h] = ap[h];
    }
    __syncwarp();

    int g = lane;
    uint64_t cq[18];
    #pragma unroll
    for (int p = 0; p < 18; p++)
        cq[p] = *(const uint64_t*)&g_Q[(p*32+g)*2];

    uint64_t acc2[10];
    #pragma unroll
    for (int h = 0; h < 10; h++) acc2[h] = 0ull;

    for (int k = 0; k < K1N; k++) {
        const ulonglong2* fp = (const ulonglong2*)&feat_s[warp][k][0];
        uint64_t sa = 0ull, sb = 0ull, sc = 0ull;
        #pragma unroll
        for (int q = 0; q < 9; q++) {
            ulonglong2 f = fp[q];
            if (q % 3 == 0)      { fma2(sa, cq[2*q], f.x); fma2(sb, cq[2*q+1], f.y); }
            else if (q % 3 == 1) { fma2(sc, cq[2*q], f.x); fma2(sa, cq[2*q+1], f.y); }
            else                 { fma2(sb, cq[2*q], f.x); fma2(sc, cq[2*q+1], f.y); }
        }
        float2 va = unpk(sa), vb = unpk(sb), vc = unpk(sc);
        float s = ((va.x + va.y) + (vb.x + vb.y)) + (vc.x + vc.y);
        float gv = __expf(-0.5f * s);
        uint64_t gd = dup2(gv);
        const ulonglong2* ap = (const ulonglong2*)&attr_s[warp][k][0];
        #pragma unroll
        for (int q = 0; q < 5; q++) {
            ulonglong2 a = ap[q];
            fma2(acc2[2*q],   gd, a.x);
            fma2(acc2[2*q+1], gd, a.y);
        }
    }
    // store pre-split bf16 pairs: k' = g*20 + h, kpair = g*10 + hp
    uint2* mp = g_Apk + (size_t)row*KPAIRS + g*10;
    #pragma unroll
    for (int hp = 0; hp < 10; hp++) {
        float2 v = unpk(acc2[hp]);
        uint32_t hi, lo;
        cvt_split(v, hi, lo);
        mp[hp] = make_uint2(hi, lo);
    }
}

// ---------------- kernel 3: HMMA GEMM, pre-split A, zero-convert mainloop ---
// smem (floats): filt_s 64x132 = 8448 | emb_s 64x33 = 2112 | embW_s 4096
#define GE_SMEM_FLOATS (8448 + 2112 + 4096)
__global__ void __launch_bounds__(256) gemm_epi_kernel(
    const float* __restrict__ opb,
    const float* __restrict__ embW, const float* __restrict__ embb,
    const float* __restrict__ betaW, const float* __restrict__ betab,
    const float* __restrict__ sattW, const float* __restrict__ sattb,
    const float* __restrict__ cattW, const float* __restrict__ cattb,
    const float* __restrict__ nodefW, const float* __restrict__ nodefb)
{
    extern __shared__ __align__(16) float sm[];
    float* filt_s = sm;            // 64 x 132
    float* emb_s  = sm + 8448;     // 64 x 33
    float* embW_s = sm + 10560;    // 128 x 32

    int t = threadIdx.x, lane = t & 31, wid = t >> 5;
    int wr = wid & 1, wc = wid >> 1;          // 2 row-groups x 4 col-groups
    int row0 = blockIdx.x * 64;
    int g = lane >> 2, tg = lane & 3;

    for (int i = t; i < DM*DH; i += 256) embW_s[i] = embW[i];

    const uint2* P0 = g_Apk + (size_t)(row0 + wr*32 +      g    ) * KPAIRS;
    const uint2* P1 = g_Apk + (size_t)(row0 + wr*32 +      g + 8) * KPAIRS;
    const uint2* P2 = g_Apk + (size_t)(row0 + wr*32 + 16 + g    ) * KPAIRS;
    const uint2* P3 = g_Apk + (size_t)(row0 + wr*32 + 16 + g + 8) * KPAIRS;
    const uint4* Bg = g_Bfrag + (wc*4)*32 + lane;

    float acc[2][4][4];
    #pragma unroll
    for (int ma = 0; ma < 2; ma++)
        #pragma unroll
        for (int j = 0; j < 4; j++)
            #pragma unroll
            for (int q = 0; q < 4; q++) acc[ma][j][q] = 0.f;

    uint2 pa[8];
    pa[0] = P0[tg];   pa[1] = P1[tg];   pa[2] = P0[tg+4]; pa[3] = P1[tg+4];
    pa[4] = P2[tg];   pa[5] = P3[tg];   pa[6] = P2[tg+4]; pa[7] = P3[tg+4];
    uint4 bbn[4];
    #pragma unroll
    for (int j = 0; j < 4; j++) bbn[j] = __ldg(Bg + j*32);

    for (int ks = 0; ks < NKS; ks++) {
        uint2 pu[8];
        #pragma unroll
        for (int r = 0; r < 8; r++) pu[r] = pa[r];
        uint4 bbu[4];
        #pragma unroll
        for (int j = 0; j < 4; j++) bbu[j] = bbn[j];

        if (ks < NKS-1) {
            int kp = (ks+1)*8 + tg;
            pa[0] = P0[kp];   pa[1] = P1[kp];   pa[2] = P0[kp+4]; pa[3] = P1[kp+4];
            pa[4] = P2[kp];   pa[5] = P3[kp];   pa[6] = P2[kp+4]; pa[7] = P3[kp+4];
            #pragma unroll
            for (int j = 0; j < 4; j++) bbn[j] = __ldg(Bg + (ks+1)*512 + j*32);
        }

        #pragma unroll
        for (int j = 0; j < 4; j++) {
            uint4 bb = bbu[j];
            hmma(acc[0][j], pu[0].x, pu[1].x, pu[2].x, pu[3].x, bb.x, bb.y);
            hmma(acc[0][j], pu[0].x, pu[1].x, pu[2].x, pu[3].x, bb.z, bb.w);
            hmma(acc[0][j], pu[0].y, pu[1].y, pu[2].y, pu[3].y, bb.x, bb.y);
            hmma(acc[1][j], pu[4].x, pu[5].x, pu[6].x, pu[7].x, bb.x, bb.y);
            hmma(acc[1][j], pu[4].x, pu[5].x, pu[6].x, pu[7].x, bb.z, bb.w);
            hmma(acc[1][j], pu[4].y, pu[5].y, pu[6].y, pu[7].y, bb.x, bb.y);
        }
    }

    #pragma unroll
    for (int ma = 0; ma < 2; ma++) {
        int r0 = wr*32 + ma*16 + g;
        #pragma unroll
        for (int j = 0; j < 4; j++) {
            int c = wc*32 + j*8 + 2*tg;
            float b0 = opb[c], b1 = opb[c+1];
            filt_s[ r0     *132 + c    ] = fmaxf(acc[ma][j][0] + b0, 0.f);
            filt_s[ r0     *132 + c + 1] = fmaxf(acc[ma][j][1] + b1, 0.f);
            filt_s[(r0+8)  *132 + c    ] = fmaxf(acc[ma][j][2] + b0, 0.f);
            filt_s[(r0+8)  *132 + c + 1] = fmaxf(acc[ma][j][3] + b1, 0.f);
        }
    }
    __syncthreads();

    {
        int r  = t >> 2;
        int jb = (t & 3) * 8;
        uint64_t s2[4];
        #pragma unroll
        for (int q = 0; q < 4; q++) {
            float2 bb = make_float2(embb[jb+2*q], embb[jb+2*q+1]);
            s2[q] = *(const uint64_t*)&bb;
        }
        #pragma unroll 4
        for (int c = 0; c < DM; c++) {
            uint64_t fd = dup2(filt_s[r*132 + c]);
            ulonglong2 w0 = *(const ulonglong2*)&embW_s[c*DH + jb];
            ulonglong2 w1 = *(const ulonglong2*)&embW_s[c*DH + jb + 4];
            fma2(s2[0], fd, w0.x); fma2(s2[1], fd, w0.y);
            fma2(s2[2], fd, w1.x); fma2(s2[3], fd, w1.y);
        }
        #pragma unroll
        for (int q = 0; q < 4; q++) {
            float2 v = unpk(s2[q]);
            emb_s[r*33 + jb + 2*q    ] = fmaxf(v.x, 0.f);
            emb_s[r*33 + jb + 2*q + 1] = fmaxf(v.y, 0.f);
        }
    }
    __syncthreads();

    if (t < 64) {
        int ri = row0 + t;
        float vb = betab[0], vs = sattb[0], vc = cattb[0];
        float n0 = nodefb[0], n1 = nodefb[1];
        #pragma unroll
        for (int j = 0; j < DH; j++) {
            float e = emb_s[t*33 + j];
            vb += e*betaW[j];
            vs += e*sattW[j];
            vc += e*cattW[j];
            n0 += e*nodefW[j*2+0];
            n1 += e*nodefW[j*2+1];
        }
        g_beta[ri]      = fmaxf(vb, 0.f);
        g_satt[ri]      = fmaxf(vs, 0.f);
        g_catt[ri]      = fmaxf(vc, 0.f);
        g_nodef[ri*2+0] = fmaxf(n0, 0.f);
        g_nodef[ri*2+1] = fmaxf(n1, 0.f);
    }
}

// ---------------- kernel 4: stage-2, lane=k, quadratic-form gaussians -------
__global__ void __launch_bounds__(256) stage2_kernel(
    const float* __restrict__ frame, const int* __restrict__ seq,
    const float* __restrict__ emb2W, const float* __restrict__ emb2b,
    float* __restrict__ out)
{
    __shared__ __align__(8) float q2_s[11*32*2];
    __shared__ float w2_s[32];
    for (int i = threadIdx.x; i < 11*32*2; i += 256) q2_s[i] = g_Q2[i];
    if (threadIdx.x < 32) w2_s[threadIdx.x] = emb2W[threadIdx.x];
    __syncthreads();

    int warp = threadIdx.x >> 5, lane = threadIdx.x & 31;
    int row  = blockIdx.x * 8 + warp;
    int b = row >> 11, l = row & (LSEQ-1);
    const float* fb = frame + (size_t)b * LSEQ * 12;

    int j  = g_idx2[row*K2N + lane];
    int jg = b*LSEQ + j;

    float cix = fb[l*12+0], ciy = fb[l*12+1], ciz = fb[l*12+2];
    float zix = fb[l*12+9], ziy = fb[l*12+10], ziz = fb[l*12+11];
    float cjx = fb[j*12+0], cjy = fb[j*12+1], cjz = fb[j*12+2];
    float zjx = fb[j*12+9], zjy = fb[j*12+10], zjz = fb[j*12+11];
    float dx = cjx-cix, dy = cjy-ciy, dz = cjz-ciz;
    float dist = sqrtf(dx*dx + dy*dy + dz*dz + 1e-12f);
    float x0 = dist;
    float x1 = zix*zjx + ziy*zjy + ziz*zjz;
    float x2 = (dx*zjx + dy*zjy + dz*zjz) / dist;
    float x3 = (zix*dx + ziy*dy + ziz*dz) / dist;
    float seqi = (float)seq[b*LSEQ+l];
    float seqj = (float)seq[jg];
    float x4 = fminf(fabsf(seqj-seqi), 8.0f);

    float fv[22];
    fv[0]=x0; fv[1]=x1; fv[2]=x2; fv[3]=x3; fv[4]=x4;
    fv[5]=x0*x0;  fv[6]=x0*x1;  fv[7]=x0*x2;  fv[8]=x0*x3;  fv[9]=x0*x4;
    fv[10]=x1*x1; fv[11]=x1*x2; fv[12]=x1*x3; fv[13]=x1*x4;
    fv[14]=x2*x2; fv[15]=x2*x3; fv[16]=x2*x4;
    fv[17]=x3*x3; fv[18]=x3*x4;
    fv[19]=x4*x4;
    fv[20]=1.0f;  fv[21]=0.0f;
    uint64_t f2[11];
    #pragma unroll
    for (int p = 0; p < 11; p++) {
        float2 pp = make_float2(fv[2*p], fv[2*p+1]);
        f2[p] = *(const uint64_t*)&pp;
    }

    float gw = emb2b[0];
    const uint64_t* qb = (const uint64_t*)q2_s;
    #pragma unroll 4
    for (int n = 0; n < NG; n++) {
        uint64_t sa = 0ull, sb = 0ull, sc = 0ull;
        #pragma unroll
        for (int p = 0; p < 11; p++) {
            uint64_t q = qb[p*32 + n];
            if (p % 3 == 0)      fma2(sa, f2[p], q);
            else if (p % 3 == 1) fma2(sb, f2[p], q);
            else                 fma2(sc, f2[p], q);
        }
        float2 va = unpk(sa), vb2 = unpk(sb), vc2 = unpk(sc);
        float s = ((va.x + va.y) + (vb2.x + vb2.y)) + (vc2.x + vc2.y);
        gw = __fmaf_rn(__expf(s), w2_s[n], gw);
    }
    gw = fmaxf(gw, 0.f);

    float e = (lane == 0) ? g_satt[row] : g_catt[jg];
    float logit = g_beta[row] * e;
    float mx = logit;
    #pragma unroll
    for (int off = 16; off > 0; off >>= 1)
        mx = fmaxf(mx, __shfl_xor_sync(0xffffffffu, mx, off));
    float w = gw * __expf(logit - mx);
    float sw = w;
    #pragma unroll
    for (int off = 16; off > 0; off >>= 1)
        sw += __shfl_xor_sync(0xffffffffu, sw, off);
    float a = w / (sw + 1e-6f);
    float o0 = a * g_nodef[jg*2+0];
    float o1 = a * g_nodef[jg*2+1];
    #pragma unroll
    for (int off = 16; off > 0; off >>= 1) {
        o0 += __shfl_xor_sync(0xffffffffu, o0, off);
        o1 += __shfl_xor_sync(0xffffffffu, o1, off);
    }
    if (lane == 0) { out[row*2+0] = o0; out[row*2+1] = o1; }
}

// ---------------- launcher --------------------------------------------------
extern "C" void kernel_launch(void* const* d_in, const int* in_sizes, int n_in,
                              void* d_out, int out_size)
{
    const float* attr        = (const float*)d_in[0];
    const float* frame       = (const float*)d_in[1];
    const int*   seq         = (const int*)  d_in[2];
    const float* gk1_centers = (const float*)d_in[3];
    const float* gk1_prec    = (const float*)d_in[4];
    const float* opk         = (const float*)d_in[5];
    const float* opb         = (const float*)d_in[6];
    const float* embW        = (const float*)d_in[7];
    const float* embb        = (const float*)d_in[8];
    const float* betaW       = (const float*)d_in[9];
    const float* betab       = (const float*)d_in[10];
    const float* sattW       = (const float*)d_in[11];
    const float* sattb       = (const float*)d_in[12];
    const float* cattW       = (const float*)d_in[13];
    const float* cattb       = (const float*)d_in[14];
    const float* nodefW      = (const float*)d_in[15];
    const float* nodefb      = (const float*)d_in[16];
    const float* gk2_centers = (const float*)d_in[17];
    const float* gk2_prec    = (const float*)d_in[18];
    const float* emb2W       = (const float*)d_in[19];
    const float* emb2b       = (const float*)d_in[20];
    float* out = (float*)d_out;

    cudaFuncSetAttribute(gemm_epi_kernel,
                         cudaFuncAttributeMaxDynamicSharedMemorySize,
                         GE_SMEM_FLOATS * 4);

    prep_kernel<<<146, 256>>>(frame, opk, gk1_centers, gk1_prec,
                              gk2_centers, gk2_prec);
    knn_kernel<<<NROWS/8, 256>>>();
    stage1_kernel<<<NROWS/8, 256>>>(frame, attr, seq);
    gemm_epi_kernel<<<NROWS/64, 256, GE_SMEM_FLOATS*4>>>(
        opb, embW, embb, betaW, betab,
        sattW, sattb, cattW, cattb, nodefW, nodefb);
    stage2_kernel<<<NROWS/8, 256>>>(frame, seq, emb2W, emb2b, out);
}

// round 15
// speedup vs baseline: 1.0145x; 1.0145x over previous
#include <cuda_runtime.h>
#include <math_constants.h>
#include <cstdint>

#define LSEQ 2048
#define BATCH 8
#define NROWS (BATCH*LSEQ)
#define K2N 32
#define K1N 16
#define NG 32
#define HIN 20
#define DM 128
#define DH 32
#define KDIM 640   // NG*HIN
#define NKS 40     // KDIM/16
#define NTILES (NROWS/16)

// ---------------- device scratch (static, no allocation) ----------------
__device__ float4 g_cpack[NROWS];
__device__ int   g_idx2[NROWS*K2N];
// A in HMMA fragment order: [tile16][ks][lane][reg] = uint2{bf16x2 hi, bf16x2 lo}
__device__ __align__(16) uint2 g_Afrag[(size_t)NTILES*NKS*128];
__device__ float g_satt[NROWS];
__device__ float g_catt[NROWS];
__device__ float g_beta[NROWS];
__device__ float g_nodef[NROWS*2];
__device__ uint4 g_Bfrag[NKS*16*32];
__device__ float g_Q[18*32*2];
__device__ float g_Q2[11*32*2];

// ---------------- helpers ----------------
__device__ __forceinline__ void cvt_split(float2 v, uint32_t& h, uint32_t& l) {
    uint32_t hh;
    asm("cvt.rn.bf16x2.f32 %0, %1, %2;" : "=r"(hh) : "f"(v.y), "f"(v.x));
    float hx = __uint_as_float(hh << 16);
    float hy = __uint_as_float(hh & 0xffff0000u);
    float lx = v.x - hx, ly = v.y - hy;
    uint32_t ll;
    asm("cvt.rn.bf16x2.f32 %0, %1, %2;" : "=r"(ll) : "f"(ly), "f"(lx));
    h = hh; l = ll;
}
__device__ __forceinline__ void hmma(float* d, uint32_t a0, uint32_t a1,
                                     uint32_t a2, uint32_t a3,
                                     uint32_t b0, uint32_t b1) {
    asm("mma.sync.aligned.m16n8k16.row.col.f32.bf16.bf16.f32 "
        "{%0,%1,%2,%3}, {%4,%5,%6,%7}, {%8,%9}, {%0,%1,%2,%3};"
        : "+f"(d[0]), "+f"(d[1]), "+f"(d[2]), "+f"(d[3])
        : "r"(a0), "r"(a1), "r"(a2), "r"(a3), "r"(b0), "r"(b1));
}
__device__ __forceinline__ void fma2(uint64_t& d, uint64_t a, uint64_t b) {
    asm("fma.rn.f32x2 %0, %1, %2, %0;" : "+l"(d) : "l"(a), "l"(b));
}
__device__ __forceinline__ uint64_t dup2(float x) {
    uint64_t r; uint32_t u = __float_as_uint(x);
    asm("mov.b64 %0, {%1, %1};" : "=l"(r) : "r"(u));
    return r;
}
__device__ __forceinline__ float2 unpk(uint64_t v) {
    float lo, hi;
    asm("mov.b64 {%0, %1}, %2;" : "=f"(lo), "=f"(hi) : "l"(v));
    return make_float2(lo, hi);
}
__device__ __forceinline__ float knn_dist(float cx2, float cy2, float cz2,
                                          float ciw, float4 cm) {
    float s = __fmaf_rn(cz2, cm.z, cm.w + ciw);
    s = __fmaf_rn(cy2, cm.y, s);
    s = __fmaf_rn(cx2, cm.x, s);
    return fmaxf(s, 0.f);
}

// ---------------- kernel 0: merged prep (pack | bprep | qprep | qprep2) -----
__global__ void __launch_bounds__(256) prep_kernel(
    const float* __restrict__ frame, const float* __restrict__ opk,
    const float* __restrict__ gk1_centers, const float* __restrict__ gk1_prec,
    const float* __restrict__ gk2_centers, const float* __restrict__ gk2_prec)
{
    int bid = blockIdx.x, tid = threadIdx.x;
    if (bid < 64) {
        int i = bid * 256 + tid;
        const float* f = frame + (size_t)i * 12;
        float x = f[0], y = f[1], z = f[2];
        g_cpack[i] = make_float4(x, y, z, x*x + y*y + z*z);
    } else if (bid < 144) {
        int idx = (bid - 64) * 256 + tid;
        int lane = idx & 31, na = (idx >> 5) & 15, ks = idx >> 9;
        int g = lane >> 2, t = lane & 3;
        int n = na*8 + g;
        int kb = ks*16 + 2*t;
        float2 p0 = make_float2(opk[(kb  )*DM + n], opk[(kb+1)*DM + n]);
        float2 p1 = make_float2(opk[(kb+8)*DM + n], opk[(kb+9)*DM + n]);
        uint32_t h0,l0,h1,l1;
        cvt_split(p0, h0, l0);
        cvt_split(p1, h1, l1);
        g_Bfrag[idx] = make_uint4(h0, h1, l0, l1);
    } else if (bid == 144) {
        if (tid >= 32) return;
        int g = tid;
        float P[7][7], c[7];
        #pragma unroll
        for (int d = 0; d < 7; d++) {
            c[d] = gk1_centers[d*NG + g];
            #pragma unroll
            for (int k = 0; k < 7; k++) P[d][k] = gk1_prec[(d*7+k)*NG + g];
        }
        float A[7][7];
        #pragma unroll
        for (int d = 0; d < 7; d++)
            #pragma unroll
            for (int e = 0; e < 7; e++) {
                float s = 0.f;
                #pragma unroll
                for (int k = 0; k < 7; k++) s += P[d][k]*P[e][k];
                A[d][e] = s;
            }
        float coeff[36];
        #pragma unroll
        for (int d = 0; d < 7; d++) {
            float s = 0.f;
            #pragma unroll
            for (int e = 0; e < 7; e++) s += A[d][e]*c[e];
            coeff[d] = -2.f*s;
        }
        int i = 7;
        #pragma unroll
        for (int d = 0; d < 7; d++)
            #pragma unroll
            for (int e = 0; e < 7; e++)
                if (e >= d) coeff[i++] = A[d][e]*((d==e)?1.f:2.f);
        float cc = 0.f;
        #pragma unroll
        for (int d = 0; d < 7; d++)
            #pragma unroll
            for (int e = 0; e < 7; e++) cc += c[d]*A[d][e]*c[e];
        coeff[35] = cc;
        #pragma unroll
        for (int p = 0; p < 18; p++) {
            g_Q[(p*32+g)*2 + 0] = coeff[2*p];
            g_Q[(p*32+g)*2 + 1] = coeff[2*p+1];
        }
    } else {
        if (tid >= 32) return;
        int g = tid;
        float P[5][5], c[5];
        #pragma unroll
        for (int d = 0; d < 5; d++) {
            c[d] = gk2_centers[d*NG + g];
            #pragma unroll
            for (int k = 0; k < 5; k++) P[d][k] = gk2_prec[(d*5+k)*NG + g];
        }
        float A[5][5];
        #pragma unroll
        for (int d = 0; d < 5; d++)
            #pragma unroll
            for (int e = 0; e < 5; e++) {
                float s = 0.f;
                #pragma unroll
                for (int k = 0; k < 5; k++) s += P[d][k]*P[e][k];
                A[d][e] = s;
            }
        float coeff[22];
        #pragma unroll
        for (int d = 0; d < 5; d++) {
            float s = 0.f;
            #pragma unroll
            for (int e = 0; e < 5; e++) s += A[d][e]*c[e];
            coeff[d] = -2.f*s;
        }
        int i = 5;
        #pragma unroll
        for (int d = 0; d < 5; d++)
            #pragma unroll
            for (int e = 0; e < 5; e++)
                if (e >= d) coeff[i++] = A[d][e]*((d==e)?1.f:2.f);
        float cc = 0.f;
        #pragma unroll
        for (int d = 0; d < 5; d++)
            #pragma unroll
            for (int e = 0; e < 5; e++) cc += c[d]*A[d][e]*c[e];
        coeff[20] = cc;
        coeff[21] = 0.f;
        #pragma unroll
        for (int p = 0; p < 11; p++) {
            g_Q2[(p*32+g)*2 + 0] = -0.5f*coeff[2*p];
            g_Q2[(p*32+g)*2 + 1] = -0.5f*coeff[2*p+1];
        }
    }
}

// ---------------- kernel 1: 32-NN, bf16 d-cache + threshold + exact rank ----
__global__ void __launch_bounds__(256) knn_kernel()
{
    __shared__ uint32_t dc_s[8][32][32];
    __shared__ unsigned long long buf_s[8][64];
    __shared__ int idx_s[8][64];
    int warp = threadIdx.x >> 5, lane = threadIdx.x & 31;
    int row  = blockIdx.x * 8 + warp;
    int b = row >> 11, l = row & (LSEQ-1);
    const float4* cb = g_cpack + (size_t)b * LSEQ;
    float4 ci = cb[l];
    float cx2 = -2.f*ci.x, cy2 = -2.f*ci.y, cz2 = -2.f*ci.z, ciw = ci.w;

    float v0 = CUDART_INF_F, v1 = CUDART_INF_F, v2 = CUDART_INF_F, v3 = CUDART_INF_F;
    uint32_t* dc = &dc_s[warp][0][0];
    #pragma unroll 2
    for (int t2 = 0; t2 < 32; t2++) {
        float4 ca = cb[t2*64 + lane];
        float4 cbq = cb[t2*64 + 32 + lane];
        float d0 = knn_dist(cx2, cy2, cz2, ciw, ca);
        float d1 = knn_dist(cx2, cy2, cz2, ciw, cbq);
        float a0, a1, a2;
        a0 = fmaxf(v0, d0); v0 = fminf(v0, d0);
        a1 = fmaxf(v1, a0); v1 = fminf(v1, a0);
        a2 = fmaxf(v2, a1); v2 = fminf(v2, a1);
        v3 = fminf(v3, a2);
        a0 = fmaxf(v0, d1); v0 = fminf(v0, d1);
        a1 = fmaxf(v1, a0); v1 = fminf(v1, a0);
        a2 = fmaxf(v2, a1); v2 = fminf(v2, a1);
        v3 = fminf(v3, a2);
        uint32_t pair;
        asm("cvt.rn.bf16x2.f32 %0, %1, %2;" : "=r"(pair) : "f"(d1), "f"(d0));
        dc[t2*32 + lane] = pair;
    }

    float T = 0.f;
    for (int s = 0; s < K2N; s++) {
        unsigned mnb  = __reduce_min_sync(0xffffffffu, __float_as_uint(v0));
        unsigned ball = __ballot_sync(0xffffffffu, __float_as_uint(v0) == mnb);
        if (lane == __ffs(ball) - 1) { v0 = v1; v1 = v2; v2 = v3; v3 = CUDART_INF_F; }
        T = __uint_as_float(mnb);
    }
    uint32_t Tb;
    asm("cvt.rn.bf16x2.f32 %0, %1, %1;" : "=r"(Tb) : "f"(T));

    unsigned lmask = (1u << lane) - 1u;
    int* idxw = idx_s[warp];
    int base = 0;
    for (int t2 = 0; t2 < 32; t2++) {
        uint32_t pair = dc[t2*32 + lane];
        uint32_t mask = __vcmpleu2(pair, Tb);
        bool lo = (mask & 0x0000ffffu) != 0;
        bool hi = (mask & 0xffff0000u) != 0;
        unsigned bl = __ballot_sync(0xffffffffu, lo);
        if (lo) { int pos = base + __popc(bl & lmask); if (pos < 64) idxw[pos] = t2*64 + lane; }
        base += __popc(bl);
        unsigned bh = __ballot_sync(0xffffffffu, hi);
        if (hi) { int pos = base + __popc(bh & lmask); if (pos < 64) idxw[pos] = t2*64 + 32 + lane; }
        base += __popc(bh);
    }
    __syncwarp();

    int n = min(base, 64);
    unsigned long long* buf = buf_s[warp];
    for (int c = lane; c < n; c += 32) {
        int m = idxw[c];
        float4 cm = cb[m];
        float d = knn_dist(cx2, cy2, cz2, ciw, cm);
        buf[c] = ((unsigned long long)__float_as_uint(d) << 32) | (unsigned)m;
    }
    __syncwarp();
    for (int c = lane; c < n; c += 32) {
        unsigned long long x = buf[c];
        int r = 0;
        #pragma unroll 4
        for (int i = 0; i < n; i++) r += (buf[i] < x) ? 1 : 0;
        if (r < K2N) g_idx2[row*K2N + r] = (int)(x & 0xffffffffu);
    }
}

// ---------------- kernel 2: coords1 + gaussian dot + fragment-order store ---
__global__ void __launch_bounds__(256) stage1_kernel(
    const float* __restrict__ frame, const float* __restrict__ attr,
    const int* __restrict__ seq)
{
    __shared__ __align__(16) float attr_s[8][K1N][HIN];
    __shared__ __align__(16) float feat_s[8][K1N][36];
    int warp = threadIdx.x >> 5, lane = threadIdx.x & 31;
    int row  = blockIdx.x * 8 + warp;
    int b = row >> 11, l = row & (LSEQ-1);
    const float* fb = frame + (size_t)b * LSEQ * 12;

    if (lane < K1N) {
        int k = lane;
        int j = g_idx2[row*K2N + k];
        float fi[12];
        #pragma unroll
        for (int d = 0; d < 12; d++) fi[d] = fb[l*12+d];
        float cjx = fb[j*12+0], cjy = fb[j*12+1], cjz = fb[j*12+2];
        float zjx = fb[j*12+9], zjy = fb[j*12+10], zjz = fb[j*12+11];
        float dx = cjx - fi[0], dy = cjy - fi[1], dz = cjz - fi[2];
        float dist = sqrtf(dx*dx + dy*dy + dz*dz + 1e-12f);
        float x[7];
        x[0] = dx*fi[3] + dy*fi[4] + dz*fi[5];
        x[1] = dx*fi[6] + dy*fi[7] + dz*fi[8];
        x[2] = dx*fi[9] + dy*fi[10] + dz*fi[11];
        float seqi = (float)seq[b*LSEQ + l];
        float seqj = (float)seq[b*LSEQ + j];
        x[3] = fminf(fabsf(seqj - seqi), 8.0f);
        x[4] = fi[9]*zjx + fi[10]*zjy + fi[11]*zjz;
        x[5] = (dx*zjx + dy*zjy + dz*zjz) / dist;
        x[6] = (fi[9]*dx + fi[10]*dy + fi[11]*dz) / dist;
        float fv[36];
        #pragma unroll
        for (int d = 0; d < 7; d++) fv[d] = x[d];
        int i = 7;
        #pragma unroll
        for (int d = 0; d < 7; d++)
            #pragma unroll
            for (int e = 0; e < 7; e++)
                if (e >= d) fv[i++] = x[d]*x[e];
        fv[35] = 1.0f;
        float4* fd = (float4*)&feat_s[warp][k][0];
        #pragma unroll
        for (int q = 0; q < 9; q++)
            fd[q] = make_float4(fv[4*q], fv[4*q+1], fv[4*q+2], fv[4*q+3]);
    } else {
        int k = lane - K1N;
        int j = g_idx2[row*K2N + k];
        const float2* ap = (const float2*)(attr + ((size_t)b*LSEQ + j) * HIN);
        float2* dst = (float2*)&attr_s[warp][k][0];
        #pragma unroll
        for (int h = 0; h < HIN/2; h++) dst[h] = ap[h];
    }
    __syncwarp();

    int g = lane;
    uint64_t cq[18];
    #pragma unroll
    for (int p = 0; p < 18; p++)
        cq[p] = *(const uint64_t*)&g_Q[(p*32+g)*2];

    uint64_t acc2[10];
    #pragma unroll
    for (int h = 0; h < 10; h++) acc2[h] = 0ull;

    for (int k = 0; k < K1N; k++) {
        const ulonglong2* fp = (const ulonglong2*)&feat_s[warp][k][0];
        uint64_t sa = 0ull, sb = 0ull, sc = 0ull;
        #pragma unroll
        for (int q = 0; q < 9; q++) {
            ulonglong2 f = fp[q];
            if (q % 3 == 0)      { fma2(sa, cq[2*q], f.x); fma2(sb, cq[2*q+1], f.y); }
            else if (q % 3 == 1) { fma2(sc, cq[2*q], f.x); fma2(sa, cq[2*q+1], f.y); }
            else                 { fma2(sb, cq[2*q], f.x); fma2(sc, cq[2*q+1], f.y); }
        }
        float2 va = unpk(sa), vb = unpk(sb), vc = unpk(sc);
        float s = ((va.x + va.y) + (vb.x + vb.y)) + (vc.x + vc.y);
        float gv = __expf(-0.5f * s);
        uint64_t gd = dup2(gv);
        const ulonglong2* ap = (const ulonglong2*)&attr_s[warp][k][0];
        #pragma unroll
        for (int q = 0; q < 5; q++) {
            ulonglong2 a = ap[q];
            fma2(acc2[2*q],   gd, a.x);
            fma2(acc2[2*q+1], gd, a.y);
        }
    }
    // scatter to HMMA fragment layout: k' = g*20 + 2*hp(+1)
    {
        int tile = row >> 4, r = row & 15;
        int rlow4 = (r & 7) * 4, rtop = r >> 3;
        #pragma unroll
        for (int hp = 0; hp < 10; hp++) {
            float2 v = unpk(acc2[hp]);
            uint32_t hi, lo;
            cvt_split(v, hi, lo);
            int pp = g*10 + hp;
            int ks = pp >> 3, p = pp & 7;
            int lanep = rlow4 + (p & 3);
            int ridx = rtop + ((p >> 2) << 1);
            g_Afrag[((size_t)(tile*NKS + ks) << 7) + lanep*4 + ridx] =
                make_uint2(hi, lo);
        }
    }
}

// ---------------- kernel 3: HMMA GEMM, fragment-layout A, coalesced ---------
// smem (floats): filt_s 64x132 = 8448 | emb_s 64x33 = 2112 | embW_s 4096
#define GE_SMEM_FLOATS (8448 + 2112 + 4096)
__global__ void __launch_bounds__(256) gemm_epi_kernel(
    const float* __restrict__ opb,
    const float* __restrict__ embW, const float* __restrict__ embb,
    const float* __restrict__ betaW, const float* __restrict__ betab,
    const float* __restrict__ sattW, const float* __restrict__ sattb,
    const float* __restrict__ cattW, const float* __restrict__ cattb,
    const float* __restrict__ nodefW, const float* __restrict__ nodefb)
{
    extern __shared__ __align__(16) float sm[];
    float* filt_s = sm;            // 64 x 132
    float* emb_s  = sm + 8448;     // 64 x 33
    float* embW_s = sm + 10560;    // 128 x 32

    int t = threadIdx.x, lane = t & 31, wid = t >> 5;
    int wr = wid & 1, wc = wid >> 1;
    int row0 = blockIdx.x * 64;
    int g = lane >> 2, tg = lane & 3;

    for (int i = t; i < DM*DH; i += 256) embW_s[i] = embW[i];

    int tile0 = blockIdx.x*4 + wr*2;
    const uint4* Af0 = (const uint4*)g_Afrag + ((size_t)tile0     * NKS) * 64 + lane*2;
    const uint4* Af1 = (const uint4*)g_Afrag + ((size_t)(tile0+1) * NKS) * 64 + lane*2;
    const uint4* Bg  = g_Bfrag + (wc*4)*32 + lane;

    float acc[2][4][4];
    #pragma unroll
    for (int ma = 0; ma < 2; ma++)
        #pragma unroll
        for (int j = 0; j < 4; j++)
            #pragma unroll
            for (int q = 0; q < 4; q++) acc[ma][j][q] = 0.f;

    uint4 an[4];
    an[0] = Af0[0]; an[1] = Af0[1]; an[2] = Af1[0]; an[3] = Af1[1];
    uint4 bbn[4];
    #pragma unroll
    for (int j = 0; j < 4; j++) bbn[j] = __ldg(Bg + j*32);

    for (int ks = 0; ks < NKS; ks++) {
        uint4 au[4];
        #pragma unroll
        for (int r = 0; r < 4; r++) au[r] = an[r];
        uint4 bbu[4];
        #pragma unroll
        for (int j = 0; j < 4; j++) bbu[j] = bbn[j];

        if (ks < NKS-1) {
            int o = (ks+1)*64;
            an[0] = Af0[o]; an[1] = Af0[o+1]; an[2] = Af1[o]; an[3] = Af1[o+1];
            #pragma unroll
            for (int j = 0; j < 4; j++) bbn[j] = __ldg(Bg + (ks+1)*512 + j*32);
        }

        #pragma unroll
        for (int j = 0; j < 4; j++) {
            uint4 bb = bbu[j];
            hmma(acc[0][j], au[0].x, au[0].z, au[1].x, au[1].z, bb.x, bb.y);
            hmma(acc[0][j], au[0].x, au[0].z, au[1].x, au[1].z, bb.z, bb.w);
            hmma(acc[0][j], au[0].y, au[0].w, au[1].y, au[1].w, bb.x, bb.y);
            hmma(acc[1][j], au[2].x, au[2].z, au[3].x, au[3].z, bb.x, bb.y);
            hmma(acc[1][j], au[2].x, au[2].z, au[3].x, au[3].z, bb.z, bb.w);
            hmma(acc[1][j], au[2].y, au[2].w, au[3].y, au[3].w, bb.x, bb.y);
        }
    }

    #pragma unroll
    for (int ma = 0; ma < 2; ma++) {
        int r0 = wr*32 + ma*16 + g;
        #pragma unroll
        for (int j = 0; j < 4; j++) {
            int c = wc*32 + j*8 + 2*tg;
            float b0 = opb[c], b1 = opb[c+1];
            filt_s[ r0     *132 + c    ] = fmaxf(acc[ma][j][0] + b0, 0.f);
            filt_s[ r0     *132 + c + 1] = fmaxf(acc[ma][j][1] + b1, 0.f);
            filt_s[(r0+8)  *132 + c    ] = fmaxf(acc[ma][j][2] + b0, 0.f);
            filt_s[(r0+8)  *132 + c + 1] = fmaxf(acc[ma][j][3] + b1, 0.f);
        }
    }
    __syncthreads();

    {
        int r  = t >> 2;
        int jb = (t & 3) * 8;
        uint64_t s2[4];
        #pragma unroll
        for (int q = 0; q < 4; q++) {
            float2 bb = make_float2(embb[jb+2*q], embb[jb+2*q+1]);
            s2[q] = *(const uint64_t*)&bb;
        }
        #pragma unroll 4
        for (int c = 0; c < DM; c++) {
            uint64_t fd = dup2(filt_s[r*132 + c]);
            ulonglong2 w0 = *(const ulonglong2*)&embW_s[c*DH + jb];
            ulonglong2 w1 = *(const ulonglong2*)&embW_s[c*DH + jb + 4];
            fma2(s2[0], fd, w0.x); fma2(s2[1], fd, w0.y);
            fma2(s2[2], fd, w1.x); fma2(s2[3], fd, w1.y);
        }
        #pragma unroll
        for (int q = 0; q < 4; q++) {
            float2 v = unpk(s2[q]);
            emb_s[r*33 + jb + 2*q    ] = fmaxf(v.x, 0.f);
            emb_s[r*33 + jb + 2*q + 1] = fmaxf(v.y, 0.f);
        }
    }
    __syncthreads();

    if (t < 64) {
        int ri = row0 + t;
        float vb = betab[0], vs = sattb[0], vc = cattb[0];
        float n0 = nodefb[0], n1 = nodefb[1];
        #pragma unroll
        for (int j = 0; j < DH; j++) {
            float e = emb_s[t*33 + j];
            vb += e*betaW[j];
            vs += e*sattW[j];
            vc += e*cattW[j];
            n0 += e*nodefW[j*2+0];
            n1 += e*nodefW[j*2+1];
        }
        g_beta[ri]      = fmaxf(vb, 0.f);
        g_satt[ri]      = fmaxf(vs, 0.f);
        g_catt[ri]      = fmaxf(vc, 0.f);
        g_nodef[ri*2+0] = fmaxf(n0, 0.f);
        g_nodef[ri*2+1] = fmaxf(n1, 0.f);
    }
}

// ---------------- kernel 4: stage-2, lane=k, quadratic-form gaussians -------
__global__ void __launch_bounds__(256) stage2_kernel(
    const float* __restrict__ frame, const int* __restrict__ seq,
    const float* __restrict__ emb2W, const float* __restrict__ emb2b,
    float* __restrict__ out)
{
    __shared__ __align__(8) float q2_s[11*32*2];
    __shared__ float w2_s[32];
    for (int i = threadIdx.x; i < 11*32*2; i += 256) q2_s[i] = g_Q2[i];
    if (threadIdx.x < 32) w2_s[threadIdx.x] = emb2W[threadIdx.x];
    __syncthreads();

    int warp = threadIdx.x >> 5, lane = threadIdx.x & 31;
    int row  = blockIdx.x * 8 + warp;
    int b = row >> 11, l = row & (LSEQ-1);
    const float* fb = frame + (size_t)b * LSEQ * 12;

    int j  = g_idx2[row*K2N + lane];
    int jg = b*LSEQ + j;

    float cix = fb[l*12+0], ciy = fb[l*12+1], ciz = fb[l*12+2];
    float zix = fb[l*12+9], ziy = fb[l*12+10], ziz = fb[l*12+11];
    float cjx = fb[j*12+0], cjy = fb[j*12+1], cjz = fb[j*12+2];
    float zjx = fb[j*12+9], zjy = fb[j*12+10], zjz = fb[j*12+11];
    float dx = cjx-cix, dy = cjy-ciy, dz = cjz-ciz;
    float dist = sqrtf(dx*dx + dy*dy + dz*dz + 1e-12f);
    float x0 = dist;
    float x1 = zix*zjx + ziy*zjy + ziz*zjz;
    float x2 = (dx*zjx + dy*zjy + dz*zjz) / dist;
    float x3 = (zix*dx + ziy*dy + ziz*dz) / dist;
    float seqi = (float)seq[b*LSEQ+l];
    float seqj = (float)seq[jg];
    float x4 = fminf(fabsf(seqj-seqi), 8.0f);

    float fv[22];
    fv[0]=x0; fv[1]=x1; fv[2]=x2; fv[3]=x3; fv[4]=x4;
    fv[5]=x0*x0;  fv[6]=x0*x1;  fv[7]=x0*x2;  fv[8]=x0*x3;  fv[9]=x0*x4;
    fv[10]=x1*x1; fv[11]=x1*x2; fv[12]=x1*x3; fv[13]=x1*x4;
    fv[14]=x2*x2; fv[15]=x2*x3; fv[16]=x2*x4;
    fv[17]=x3*x3; fv[18]=x3*x4;
    fv[19]=x4*x4;
    fv[20]=1.0f;  fv[21]=0.0f;
    uint64_t f2[11];
    #pragma unroll
    for (int p = 0; p < 11; p++) {
        float2 pp = make_float2(fv[2*p], fv[2*p+1]);
        f2[p] = *(const uint64_t*)&pp;
    }

    float gw = emb2b[0];
    const uint64_t* qb = (const uint64_t*)q2_s;
    #pragma unroll 4
    for (int n = 0; n < NG; n++) {
        uint64_t sa = 0ull, sb = 0ull, sc = 0ull;
        #pragma unroll
        for (int p = 0; p < 11; p++) {
            uint64_t q = qb[p*32 + n];
            if (p % 3 == 0)      fma2(sa, f2[p], q);
            else if (p % 3 == 1) fma2(sb, f2[p], q);
            else                 fma2(sc, f2[p], q);
        }
        float2 va = unpk(sa), vb2 = unpk(sb), vc2 = unpk(sc);
        float s = ((va.x + va.y) + (vb2.x + vb2.y)) + (vc2.x + vc2.y);
        gw = __fmaf_rn(__expf(s), w2_s[n], gw);
    }
    gw = fmaxf(gw, 0.f);

    float e = (lane == 0) ? g_satt[row] : g_catt[jg];
    float logit = g_beta[row] * e;
    float mx = logit;
    #pragma unroll
    for (int off = 16; off > 0; off >>= 1)
        mx = fmaxf(mx, __shfl_xor_sync(0xffffffffu, mx, off));
    float w = gw * __expf(logit - mx);
    float sw = w;
    #pragma unroll
    for (int off = 16; off > 0; off >>= 1)
        sw += __shfl_xor_sync(0xffffffffu, sw, off);
    float a = w / (sw + 1e-6f);
    float o0 = a * g_nodef[jg*2+0];
    float o1 = a * g_nodef[jg*2+1];
    #pragma unroll
    for (int off = 16; off > 0; off >>= 1) {
        o0 += __shfl_xor_sync(0xffffffffu, o0, off);
        o1 += __shfl_xor_sync(0xffffffffu, o1, off);
    }
    if (lane == 0) { out[row*2+0] = o0; out[row*2+1] = o1; }
}

// ---------------- launcher --------------------------------------------------
extern "C" void kernel_launch(void* const* d_in, const int* in_sizes, int n_in,
                              void* d_out, int out_size)
{
    const float* attr        = (const float*)d_in[0];
    const float* frame       = (const float*)d_in[1];
    const int*   seq         = (const int*)  d_in[2];
    const float* gk1_centers = (const float*)d_in[3];
    const float* gk1_prec    = (const float*)d_in[4];
    const float* opk         = (const float*)d_in[5];
    const float* opb         = (const float*)d_in[6];
    const float* embW        = (const float*)d_in[7];
    const float* embb        = (const float*)d_in[8];
    const float* betaW       = (const float*)d_in[9];
    const float* betab       = (const float*)d_in[10];
    const float* sattW       = (const float*)d_in[11];
    const float* sattb       = (const float*)d_in[12];
    const float* cattW       = (const float*)d_in[13];
    const float* cattb       = (const float*)d_in[14];
    const float* nodefW      = (const float*)d_in[15];
    const float* nodefb      = (const float*)d_in[16];
    const float* gk2_centers = (const float*)d_in[17];
    const float* gk2_prec    = (const float*)d_in[18];
    const float* emb2W       = (const float*)d_in[19];
    const float* emb2b       = (const float*)d_in[20];
    float* out = (float*)d_out;

    cudaFuncSetAttribute(gemm_epi_kernel,
                         cudaFuncAttributeMaxDynamicSharedMemorySize,
                         GE_SMEM_FLOATS * 4);

    prep_kernel<<<146, 256>>>(frame, opk, gk1_centers, gk1_prec,
                              gk2_centers, gk2_prec);
    knn_kernel<<<NROWS/8, 256>>>();
    stage1_kernel<<<NROWS/8, 256>>>(frame, attr, seq);
    gemm_epi_kernel<<<NROWS/64, 256, GE_SMEM_FLOATS*4>>>(
        opb, embW, embb, betaW, betab,
        sattW, sattb, cattW, cattb, nodefW, nodefb);
    stage2_kernel<<<NROWS/8, 256>>>(frame, seq, emb2W, emb2b, out);
}

// round 16
// speedup vs baseline: 1.0842x; 1.0687x over previous
#include <cuda_runtime.h>
#include <math_constants.h>
#include <cstdint>

#define LSEQ 2048
#define BATCH 8
#define NROWS (BATCH*LSEQ)
#define K2N 32
#define K1N 16
#define NG 32
#define HIN 20
#define DM 128
#define DH 32
#define KDIM 640   // NG*HIN
#define NKS 40     // KDIM/16

// ---------------- device scratch (static, no allocation) ----------------
__device__ float4 g_cpack[NROWS];
__device__ int   g_idx2[NROWS*K2N];
// logical k = opk row order (g*20+h); contiguous per stage1 lane
__device__ __align__(16) float g_M[(size_t)NROWS*KDIM];
__device__ float g_satt[NROWS];
__device__ float g_catt[NROWS];
__device__ float g_beta[NROWS];
__device__ float g_nodef[NROWS*2];
// B fragments with pi: lane tg covers logical k {4tg..4tg+3} within kstep
__device__ uint4 g_Bfrag[NKS*16*32];
__device__ float g_Q[18*32*2];
__device__ float g_Q2[11*32*2];

// ---------------- helpers ----------------
__device__ __forceinline__ void cvt_split(float2 v, uint32_t& h, uint32_t& l) {
    uint32_t hh;
    asm("cvt.rn.bf16x2.f32 %0, %1, %2;" : "=r"(hh) : "f"(v.y), "f"(v.x));
    float hx = __uint_as_float(hh << 16);
    float hy = __uint_as_float(hh & 0xffff0000u);
    float lx = v.x - hx, ly = v.y - hy;
    uint32_t ll;
    asm("cvt.rn.bf16x2.f32 %0, %1, %2;" : "=r"(ll) : "f"(ly), "f"(lx));
    h = hh; l = ll;
}
__device__ __forceinline__ void hmma(float* d, uint32_t a0, uint32_t a1,
                                     uint32_t a2, uint32_t a3,
                                     uint32_t b0, uint32_t b1) {
    asm("mma.sync.aligned.m16n8k16.row.col.f32.bf16.bf16.f32 "
        "{%0,%1,%2,%3}, {%4,%5,%6,%7}, {%8,%9}, {%0,%1,%2,%3};"
        : "+f"(d[0]), "+f"(d[1]), "+f"(d[2]), "+f"(d[3])
        : "r"(a0), "r"(a1), "r"(a2), "r"(a3), "r"(b0), "r"(b1));
}
__device__ __forceinline__ void fma2(uint64_t& d, uint64_t a, uint64_t b) {
    asm("fma.rn.f32x2 %0, %1, %2, %0;" : "+l"(d) : "l"(a), "l"(b));
}
__device__ __forceinline__ uint64_t dup2(float x) {
    uint64_t r; uint32_t u = __float_as_uint(x);
    asm("mov.b64 %0, {%1, %1};" : "=l"(r) : "r"(u));
    return r;
}
__device__ __forceinline__ float2 unpk(uint64_t v) {
    float lo, hi;
    asm("mov.b64 {%0, %1}, %2;" : "=f"(lo), "=f"(hi) : "l"(v));
    return make_float2(lo, hi);
}
__device__ __forceinline__ float knn_dist(float cx2, float cy2, float cz2,
                                          float ciw, float4 cm) {
    float s = __fmaf_rn(cz2, cm.z, cm.w + ciw);
    s = __fmaf_rn(cy2, cm.y, s);
    s = __fmaf_rn(cx2, cm.x, s);
    return fmaxf(s, 0.f);
}

// ---------------- kernel 0: merged prep (pack | bprep | qprep | qprep2) -----
__global__ void __launch_bounds__(256) prep_kernel(
    const float* __restrict__ frame, const float* __restrict__ opk,
    const float* __restrict__ gk1_centers, const float* __restrict__ gk1_prec,
    const float* __restrict__ gk2_centers, const float* __restrict__ gk2_prec)
{
    int bid = blockIdx.x, tid = threadIdx.x;
    if (bid < 64) {
        int i = bid * 256 + tid;
        const float* f = frame + (size_t)i * 12;
        float x = f[0], y = f[1], z = f[2];
        g_cpack[i] = make_float4(x, y, z, x*x + y*y + z*z);
    } else if (bid < 144) {
        int idx = (bid - 64) * 256 + tid;
        int lane = idx & 31, na = (idx >> 5) & 15, ks = idx >> 9;
        int g = lane >> 2, t = lane & 3;
        int n = na*8 + g;
        int kb = ks*16 + 4*t;                      // pi: lane t -> logical {kb..kb+3}
        float2 p0 = make_float2(opk[(kb  )*DM + n], opk[(kb+1)*DM + n]);
        float2 p1 = make_float2(opk[(kb+2)*DM + n], opk[(kb+3)*DM + n]);
        uint32_t h0,l0,h1,l1;
        cvt_split(p0, h0, l0);
        cvt_split(p1, h1, l1);
        g_Bfrag[idx] = make_uint4(h0, h1, l0, l1);
    } else if (bid == 144) {
        if (tid >= 32) return;
        int g = tid;
        float P[7][7], c[7];
        #pragma unroll
        for (int d = 0; d < 7; d++) {
            c[d] = gk1_centers[d*NG + g];
            #pragma unroll
            for (int k = 0; k < 7; k++) P[d][k] = gk1_prec[(d*7+k)*NG + g];
        }
        float A[7][7];
        #pragma unroll
        for (int d = 0; d < 7; d++)
            #pragma unroll
            for (int e = 0; e < 7; e++) {
                float s = 0.f;
                #pragma unroll
                for (int k = 0; k < 7; k++) s += P[d][k]*P[e][k];
                A[d][e] = s;
            }
        float coeff[36];
        #pragma unroll
        for (int d = 0; d < 7; d++) {
            float s = 0.f;
            #pragma unroll
            for (int e = 0; e < 7; e++) s += A[d][e]*c[e];
            coeff[d] = -2.f*s;
        }
        int i = 7;
        #pragma unroll
        for (int d = 0; d < 7; d++)
            #pragma unroll
            for (int e = 0; e < 7; e++)
                if (e >= d) coeff[i++] = A[d][e]*((d==e)?1.f:2.f);
        float cc = 0.f;
        #pragma unroll
        for (int d = 0; d < 7; d++)
            #pragma unroll
            for (int e = 0; e < 7; e++) cc += c[d]*A[d][e]*c[e];
        coeff[35] = cc;
        #pragma unroll
        for (int p = 0; p < 18; p++) {
            g_Q[(p*32+g)*2 + 0] = coeff[2*p];
            g_Q[(p*32+g)*2 + 1] = coeff[2*p+1];
        }
    } else {
        if (tid >= 32) return;
        int g = tid;
        float P[5][5], c[5];
        #pragma unroll
        for (int d = 0; d < 5; d++) {
            c[d] = gk2_centers[d*NG + g];
            #pragma unroll
            for (int k = 0; k < 5; k++) P[d][k] = gk2_prec[(d*5+k)*NG + g];
        }
        float A[5][5];
        #pragma unroll
        for (int d = 0; d < 5; d++)
            #pragma unroll
            for (int e = 0; e < 5; e++) {
                float s = 0.f;
                #pragma unroll
                for (int k = 0; k < 5; k++) s += P[d][k]*P[e][k];
                A[d][e] = s;
            }
        float coeff[22];
        #pragma unroll
        for (int d = 0; d < 5; d++) {
            float s = 0.f;
            #pragma unroll
            for (int e = 0; e < 5; e++) s += A[d][e]*c[e];
            coeff[d] = -2.f*s;
        }
        int i = 5;
        #pragma unroll
        for (int d = 0; d < 5; d++)
            #pragma unroll
            for (int e = 0; e < 5; e++)
                if (e >= d) coeff[i++] = A[d][e]*((d==e)?1.f:2.f);
        float cc = 0.f;
        #pragma unroll
        for (int d = 0; d < 5; d++)
            #pragma unroll
            for (int e = 0; e < 5; e++) cc += c[d]*A[d][e]*c[e];
        coeff[20] = cc;
        coeff[21] = 0.f;
        #pragma unroll
        for (int p = 0; p < 11; p++) {
            g_Q2[(p*32+g)*2 + 0] = -0.5f*coeff[2*p];
            g_Q2[(p*32+g)*2 + 1] = -0.5f*coeff[2*p+1];
        }
    }
}

// ---------------- kernel 1: 32-NN, bf16 d-cache + threshold + exact rank ----
__global__ void __launch_bounds__(256) knn_kernel()
{
    __shared__ uint32_t dc_s[8][32][32];
    __shared__ unsigned long long buf_s[8][64];
    __shared__ int idx_s[8][64];
    int warp = threadIdx.x >> 5, lane = threadIdx.x & 31;
    int row  = blockIdx.x * 8 + warp;
    int b = row >> 11, l = row & (LSEQ-1);
    const float4* cb = g_cpack + (size_t)b * LSEQ;
    float4 ci = cb[l];
    float cx2 = -2.f*ci.x, cy2 = -2.f*ci.y, cz2 = -2.f*ci.z, ciw = ci.w;

    float v0 = CUDART_INF_F, v1 = CUDART_INF_F, v2 = CUDART_INF_F, v3 = CUDART_INF_F;
    uint32_t* dc = &dc_s[warp][0][0];
    #pragma unroll 2
    for (int t2 = 0; t2 < 32; t2++) {
        float4 ca = cb[t2*64 + lane];
        float4 cbq = cb[t2*64 + 32 + lane];
        float d0 = knn_dist(cx2, cy2, cz2, ciw, ca);
        float d1 = knn_dist(cx2, cy2, cz2, ciw, cbq);
        float a0, a1, a2;
        a0 = fmaxf(v0, d0); v0 = fminf(v0, d0);
        a1 = fmaxf(v1, a0); v1 = fminf(v1, a0);
        a2 = fmaxf(v2, a1); v2 = fminf(v2, a1);
        v3 = fminf(v3, a2);
        a0 = fmaxf(v0, d1); v0 = fminf(v0, d1);
        a1 = fmaxf(v1, a0); v1 = fminf(v1, a0);
        a2 = fmaxf(v2, a1); v2 = fminf(v2, a1);
        v3 = fminf(v3, a2);
        uint32_t pair;
        asm("cvt.rn.bf16x2.f32 %0, %1, %2;" : "=r"(pair) : "f"(d1), "f"(d0));
        dc[t2*32 + lane] = pair;
    }

    float T = 0.f;
    for (int s = 0; s < K2N; s++) {
        unsigned mnb  = __reduce_min_sync(0xffffffffu, __float_as_uint(v0));
        unsigned ball = __ballot_sync(0xffffffffu, __float_as_uint(v0) == mnb);
        if (lane == __ffs(ball) - 1) { v0 = v1; v1 = v2; v2 = v3; v3 = CUDART_INF_F; }
        T = __uint_as_float(mnb);
    }
    uint32_t Tb;
    asm("cvt.rn.bf16x2.f32 %0, %1, %1;" : "=r"(Tb) : "f"(T));

    unsigned lmask = (1u << lane) - 1u;
    int* idxw = idx_s[warp];
    int base = 0;
    for (int t2 = 0; t2 < 32; t2++) {
        uint32_t pair = dc[t2*32 + lane];
        uint32_t mask = __vcmpleu2(pair, Tb);
        bool lo = (mask & 0x0000ffffu) != 0;
        bool hi = (mask & 0xffff0000u) != 0;
        unsigned bl = __ballot_sync(0xffffffffu, lo);
        if (lo) { int pos = base + __popc(bl & lmask); if (pos < 64) idxw[pos] = t2*64 + lane; }
        base += __popc(bl);
        unsigned bh = __ballot_sync(0xffffffffu, hi);
        if (hi) { int pos = base + __popc(bh & lmask); if (pos < 64) idxw[pos] = t2*64 + 32 + lane; }
        base += __popc(bh);
    }
    __syncwarp();

    int n = min(base, 64);
    unsigned long long* buf = buf_s[warp];
    for (int c = lane; c < n; c += 32) {
        int m = idxw[c];
        float4 cm = cb[m];
        float d = knn_dist(cx2, cy2, cz2, ciw, cm);
        buf[c] = ((unsigned long long)__float_as_uint(d) << 32) | (unsigned)m;
    }
    __syncwarp();
    for (int c = lane; c < n; c += 32) {
        unsigned long long x = buf[c];
        int r = 0;
        #pragma unroll 4
        for (int i = 0; i < n; i++) r += (buf[i] < x) ? 1 : 0;
        if (r < K2N) g_idx2[row*K2N + r] = (int)(x & 0xffffffffu);
    }
}

// ---------------- kernel 2: coords1 + gaussian dot + contiguous store -------
__global__ void __launch_bounds__(256) stage1_kernel(
    const float* __restrict__ frame, const float* __restrict__ attr,
    const int* __restrict__ seq)
{
    __shared__ __align__(16) float attr_s[8][K1N][HIN];
    __shared__ __align__(16) float feat_s[8][K1N][36];
    int warp = threadIdx.x >> 5, lane = threadIdx.x & 31;
    int row  = blockIdx.x * 8 + warp;
    int b = row >> 11, l = row & (LSEQ-1);
    const float* fb = frame + (size_t)b * LSEQ * 12;

    if (lane < K1N) {
        int k = lane;
        int j = g_idx2[row*K2N + k];
        float fi[12];
        #pragma unroll
        for (int d = 0; d < 12; d++) fi[d] = fb[l*12+d];
        float cjx = fb[j*12+0], cjy = fb[j*12+1], cjz = fb[j*12+2];
        float zjx = fb[j*12+9], zjy = fb[j*12+10], zjz = fb[j*12+11];
        float dx = cjx - fi[0], dy = cjy - fi[1], dz = cjz - fi[2];
        float dist = sqrtf(dx*dx + dy*dy + dz*dz + 1e-12f);
        float x[7];
        x[0] = dx*fi[3] + dy*fi[4] + dz*fi[5];
        x[1] = dx*fi[6] + dy*fi[7] + dz*fi[8];
        x[2] = dx*fi[9] + dy*fi[10] + dz*fi[11];
        float seqi = (float)seq[b*LSEQ + l];
        float seqj = (float)seq[b*LSEQ + j];
        x[3] = fminf(fabsf(seqj - seqi), 8.0f);
        x[4] = fi[9]*zjx + fi[10]*zjy + fi[11]*zjz;
        x[5] = (dx*zjx + dy*zjy + dz*zjz) / dist;
        x[6] = (fi[9]*dx + fi[10]*dy + fi[11]*dz) / dist;
        float fv[36];
        #pragma unroll
        for (int d = 0; d < 7; d++) fv[d] = x[d];
        int i = 7;
        #pragma unroll
        for (int d = 0; d < 7; d++)
            #pragma unroll
            for (int e = 0; e < 7; e++)
                if (e >= d) fv[i++] = x[d]*x[e];
        fv[35] = 1.0f;
        float4* fd = (float4*)&feat_s[warp][k][0];
        #pragma unroll
        for (int q = 0; q < 9; q++)
            fd[q] = make_float4(fv[4*q], fv[4*q+1], fv[4*q+2], fv[4*q+3]);
    } else {
        int k = lane - K1N;
        int j = g_idx2[row*K2N + k];
        const float2* ap = (const float2*)(attr + ((size_t)b*LSEQ + j) * HIN);
        float2* dst = (float2*)&attr_s[warp][k][0];
        #pragma unroll
        for (int h = 0; h < HIN/2; h++) dst[h] = ap[h];
    }
    __syncwarp();

    int g = lane;
    uint64_t cq[18];
    #pragma unroll
    for (int p = 0; p < 18; p++)
        cq[p] = *(const uint64_t*)&g_Q[(p*32+g)*2];

    uint64_t acc2[10];
    #pragma unroll
    for (int h = 0; h < 10; h++) acc2[h] = 0ull;

    for (int k = 0; k < K1N; k++) {
        const ulonglong2* fp = (const ulonglong2*)&feat_s[warp][k][0];
        uint64_t sa = 0ull, sb = 0ull, sc = 0ull;
        #pragma unroll
        for (int q = 0; q < 9; q++) {
            ulonglong2 f = fp[q];
            if (q % 3 == 0)      { fma2(sa, cq[2*q], f.x); fma2(sb, cq[2*q+1], f.y); }
            else if (q % 3 == 1) { fma2(sc, cq[2*q], f.x); fma2(sa, cq[2*q+1], f.y); }
            else                 { fma2(sb, cq[2*q], f.x); fma2(sc, cq[2*q+1], f.y); }
        }
        float2 va = unpk(sa), vb = unpk(sb), vc = unpk(sc);
        float s = ((va.x + va.y) + (vb.x + vb.y)) + (vc.x + vc.y);
        float gv = __expf(-0.5f * s);
        uint64_t gd = dup2(gv);
        const ulonglong2* ap = (const ulonglong2*)&attr_s[warp][k][0];
        #pragma unroll
        for (int q = 0; q < 5; q++) {
            ulonglong2 a = ap[q];
            fma2(acc2[2*q],   gd, a.x);
            fma2(acc2[2*q+1], gd, a.y);
        }
    }
    // contiguous store: logical k = g*20 + h, 5 x STG.128
    {
        float4* mp = (float4*)(g_M + (size_t)row*KDIM + g*HIN);
        #pragma unroll
        for (int q = 0; q < 5; q++) {
            float2 v0 = unpk(acc2[2*q]);
            float2 v1 = unpk(acc2[2*q+1]);
            mp[q] = make_float4(v0.x, v0.y, v1.x, v1.y);
        }
    }
}

// ---------------- kernel 3: HMMA GEMM, float4 A loads, 64-row CTAs ----------
// smem (floats): filt_s 64x132 = 8448 | emb_s 64x33 = 2112 | embW_s 4096
#define GE_SMEM_FLOATS (8448 + 2112 + 4096)
__global__ void __launch_bounds__(256) gemm_epi_kernel(
    const float* __restrict__ opb,
    const float* __restrict__ embW, const float* __restrict__ embb,
    const float* __restrict__ betaW, const float* __restrict__ betab,
    const float* __restrict__ sattW, const float* __restrict__ sattb,
    const float* __restrict__ cattW, const float* __restrict__ cattb,
    const float* __restrict__ nodefW, const float* __restrict__ nodefb)
{
    extern __shared__ __align__(16) float sm[];
    float* filt_s = sm;            // 64 x 132
    float* emb_s  = sm + 8448;     // 64 x 33
    float* embW_s = sm + 10560;    // 128 x 32

    int t = threadIdx.x, lane = t & 31, wid = t >> 5;
    int wr = wid & 1, wc = wid >> 1;          // 2 row-groups x 4 col-groups
    int row0 = blockIdx.x * 64;
    int g = lane >> 2, tg = lane & 3;

    for (int i = t; i < DM*DH; i += 256) embW_s[i] = embW[i];

    // A row pointers: one float4 per row per kstep at [row][ks*16 + tg*4]
    const float* A0 = g_M + (size_t)(row0 + wr*32 +      g    ) * KDIM + tg*4;
    const float* A1 = g_M + (size_t)(row0 + wr*32 +      g + 8) * KDIM + tg*4;
    const float* A2 = g_M + (size_t)(row0 + wr*32 + 16 + g    ) * KDIM + tg*4;
    const float* A3 = g_M + (size_t)(row0 + wr*32 + 16 + g + 8) * KDIM + tg*4;
    const uint4* Bg = g_Bfrag + (wc*4)*32 + lane;

    float acc[2][4][4];
    #pragma unroll
    for (int ma = 0; ma < 2; ma++)
        #pragma unroll
        for (int j = 0; j < 4; j++)
            #pragma unroll
            for (int q = 0; q < 4; q++) acc[ma][j][q] = 0.f;

    float4 an[4];
    an[0] = *(const float4*)A0; an[1] = *(const float4*)A1;
    an[2] = *(const float4*)A2; an[3] = *(const float4*)A3;
    uint4 bbn[4];
    #pragma unroll
    for (int j = 0; j < 4; j++) bbn[j] = __ldg(Bg + j*32);

    for (int ks = 0; ks < NKS; ks++) {
        // split current A regs -> fragments (a0=k01, a2=k23 per row)
        uint32_t ah[4][2], al[4][2];
        #pragma unroll
        for (int r = 0; r < 4; r++) {
            cvt_split(make_float2(an[r].x, an[r].y), ah[r][0], al[r][0]);
            cvt_split(make_float2(an[r].z, an[r].w), ah[r][1], al[r][1]);
        }
        uint4 bbu[4];
        #pragma unroll
        for (int j = 0; j < 4; j++) bbu[j] = bbn[j];

        if (ks < NKS-1) {
            int o = (ks+1)*16;
            an[0] = *(const float4*)(A0 + o); an[1] = *(const float4*)(A1 + o);
            an[2] = *(const float4*)(A2 + o); an[3] = *(const float4*)(A3 + o);
            #pragma unroll
            for (int j = 0; j < 4; j++) bbn[j] = __ldg(Bg + (ks+1)*512 + j*32);
        }

        #pragma unroll
        for (int j = 0; j < 4; j++) {
            uint4 bb = bbu[j];
            hmma(acc[0][j], ah[0][0], ah[1][0], ah[0][1], ah[1][1], bb.x, bb.y);
            hmma(acc[0][j], ah[0][0], ah[1][0], ah[0][1], ah[1][1], bb.z, bb.w);
            hmma(acc[0][j], al[0][0], al[1][0], al[0][1], al[1][1], bb.x, bb.y);
            hmma(acc[1][j], ah[2][0], ah[3][0], ah[2][1], ah[3][1], bb.x, bb.y);
            hmma(acc[1][j], ah[2][0], ah[3][0], ah[2][1], ah[3][1], bb.z, bb.w);
            hmma(acc[1][j], al[2][0], al[3][0], al[2][1], al[3][1], bb.x, bb.y);
        }
    }

    #pragma unroll
    for (int ma = 0; ma < 2; ma++) {
        int r0 = wr*32 + ma*16 + g;
        #pragma unroll
        for (int j = 0; j < 4; j++) {
            int c = wc*32 + j*8 + 2*tg;
            float b0 = opb[c], b1 = opb[c+1];
            filt_s[ r0     *132 + c    ] = fmaxf(acc[ma][j][0] + b0, 0.f);
            filt_s[ r0     *132 + c + 1] = fmaxf(acc[ma][j][1] + b1, 0.f);
            filt_s[(r0+8)  *132 + c    ] = fmaxf(acc[ma][j][2] + b0, 0.f);
            filt_s[(r0+8)  *132 + c + 1] = fmaxf(acc[ma][j][3] + b1, 0.f);
        }
    }
    __syncthreads();

    {
        int r  = t >> 2;
        int jb = (t & 3) * 8;
        uint64_t s2[4];
        #pragma unroll
        for (int q = 0; q < 4; q++) {
            float2 bb = make_float2(embb[jb+2*q], embb[jb+2*q+1]);
            s2[q] = *(const uint64_t*)&bb;
        }
        #pragma unroll 4
        for (int c = 0; c < DM; c++) {
            uint64_t fd = dup2(filt_s[r*132 + c]);
            ulonglong2 w0 = *(const ulonglong2*)&embW_s[c*DH + jb];
            ulonglong2 w1 = *(const ulonglong2*)&embW_s[c*DH + jb + 4];
            fma2(s2[0], fd, w0.x); fma2(s2[1], fd, w0.y);
            fma2(s2[2], fd, w1.x); fma2(s2[3], fd, w1.y);
        }
        #pragma unroll
        for (int q = 0; q < 4; q++) {
            float2 v = unpk(s2[q]);
            emb_s[r*33 + jb + 2*q    ] = fmaxf(v.x, 0.f);
            emb_s[r*33 + jb + 2*q + 1] = fmaxf(v.y, 0.f);
        }
    }
    __syncthreads();

    if (t < 64) {
        int ri = row0 + t;
        float vb = betab[0], vs = sattb[0], vc = cattb[0];
        float n0 = nodefb[0], n1 = nodefb[1];
        #pragma unroll
        for (int j = 0; j < DH; j++) {
            float e = emb_s[t*33 + j];
            vb += e*betaW[j];
            vs += e*sattW[j];
            vc += e*cattW[j];
            n0 += e*nodefW[j*2+0];
            n1 += e*nodefW[j*2+1];
        }
        g_beta[ri]      = fmaxf(vb, 0.f);
        g_satt[ri]      = fmaxf(vs, 0.f);
        g_catt[ri]      = fmaxf(vc, 0.f);
        g_nodef[ri*2+0] = fmaxf(n0, 0.f);
        g_nodef[ri*2+1] = fmaxf(n1, 0.f);
    }
}

// ---------------- kernel 4: stage-2, lane=k, quadratic-form gaussians -------
__global__ void __launch_bounds__(256) stage2_kernel(
    const float* __restrict__ frame, const int* __restrict__ seq,
    const float* __restrict__ emb2W, const float* __restrict__ emb2b,
    float* __restrict__ out)
{
    __shared__ __align__(8) float q2_s[11*32*2];
    __shared__ float w2_s[32];
    for (int i = threadIdx.x; i < 11*32*2; i += 256) q2_s[i] = g_Q2[i];
    if (threadIdx.x < 32) w2_s[threadIdx.x] = emb2W[threadIdx.x];
    __syncthreads();

    int warp = threadIdx.x >> 5, lane = threadIdx.x & 31;
    int row  = blockIdx.x * 8 + warp;
    int b = row >> 11, l = row & (LSEQ-1);
    const float* fb = frame + (size_t)b * LSEQ * 12;

    int j  = g_idx2[row*K2N + lane];
    int jg = b*LSEQ + j;

    float cix = fb[l*12+0], ciy = fb[l*12+1], ciz = fb[l*12+2];
    float zix = fb[l*12+9], ziy = fb[l*12+10], ziz = fb[l*12+11];
    float cjx = fb[j*12+0], cjy = fb[j*12+1], cjz = fb[j*12+2];
    float zjx = fb[j*12+9], zjy = fb[j*12+10], zjz = fb[j*12+11];
    float dx = cjx-cix, dy = cjy-ciy, dz = cjz-ciz;
    float dist = sqrtf(dx*dx + dy*dy + dz*dz + 1e-12f);
    float x0 = dist;
    float x1 = zix*zjx + ziy*zjy + ziz*zjz;
    float x2 = (dx*zjx + dy*zjy + dz*zjz) / dist;
    float x3 = (zix*dx + ziy*dy + ziz*dz) / dist;
    float seqi = (float)seq[b*LSEQ+l];
    float seqj = (float)seq[jg];
    float x4 = fminf(fabsf(seqj-seqi), 8.0f);

    float fv[22];
    fv[0]=x0; fv[1]=x1; fv[2]=x2; fv[3]=x3; fv[4]=x4;
    fv[5]=x0*x0;  fv[6]=x0*x1;  fv[7]=x0*x2;  fv[8]=x0*x3;  fv[9]=x0*x4;
    fv[10]=x1*x1; fv[11]=x1*x2; fv[12]=x1*x3; fv[13]=x1*x4;
    fv[14]=x2*x2; fv[15]=x2*x3; fv[16]=x2*x4;
    fv[17]=x3*x3; fv[18]=x3*x4;
    fv[19]=x4*x4;
    fv[20]=1.0f;  fv[21]=0.0f;
    uint64_t f2[11];
    #pragma unroll
    for (int p = 0; p < 11; p++) {
        float2 pp = make_float2(fv[2*p], fv[2*p+1]);
        f2[p] = *(const uint64_t*)&pp;
    }

    float gw = emb2b[0];
    const uint64_t* qb = (const uint64_t*)q2_s;
    #pragma unroll 4
    for (int n = 0; n < NG; n++) {
        uint64_t sa = 0ull, sb = 0ull, sc = 0ull;
        #pragma unroll
        for (int p = 0; p < 11; p++) {
            uint64_t q = qb[p*32 + n];
            if (p % 3 == 0)      fma2(sa, f2[p], q);
            else if (p % 3 == 1) fma2(sb, f2[p], q);
            else                 fma2(sc, f2[p], q);
        }
        float2 va = unpk(sa), vb2 = unpk(sb), vc2 = unpk(sc);
        float s = ((va.x + va.y) + (vb2.x + vb2.y)) + (vc2.x + vc2.y);
        gw = __fmaf_rn(__expf(s), w2_s[n], gw);
    }
    gw = fmaxf(gw, 0.f);

    float e = (lane == 0) ? g_satt[row] : g_catt[jg];
    float logit = g_beta[row] * e;
    float mx = logit;
    #pragma unroll
    for (int off = 16; off > 0; off >>= 1)
        mx = fmaxf(mx, __shfl_xor_sync(0xffffffffu, mx, off));
    float w = gw * __expf(logit - mx);
    float sw = w;
    #pragma unroll
    for (int off = 16; off > 0; off >>= 1)
        sw += __shfl_xor_sync(0xffffffffu, sw, off);
    float a = w / (sw + 1e-6f);
    float o0 = a * g_nodef[jg*2+0];
    float o1 = a * g_nodef[jg*2+1];
    #pragma unroll
    for (int off = 16; off > 0; off >>= 1) {
        o0 += __shfl_xor_sync(0xffffffffu, o0, off);
        o1 += __shfl_xor_sync(0xffffffffu, o1, off);
    }
    if (lane == 0) { out[row*2+0] = o0; out[row*2+1] = o1; }
}

// ---------------- launcher --------------------------------------------------
extern "C" void kernel_launch(void* const* d_in, const int* in_sizes, int n_in,
                              void* d_out, int out_size)
{
    const float* attr        = (const float*)d_in[0];
    const float* frame       = (const float*)d_in[1];
    const int*   seq         = (const int*)  d_in[2];
    const float* gk1_centers = (const float*)d_in[3];
    const float* gk1_prec    = (const float*)d_in[4];
    const float* opk         = (const float*)d_in[5];
    const float* opb         = (const float*)d_in[6];
    const float* embW        = (const float*)d_in[7];
    const float* embb        = (const float*)d_in[8];
    const float* betaW       = (const float*)d_in[9];
    const float* betab       = (const float*)d_in[10];
    const float* sattW       = (const float*)d_in[11];
    const float* sattb       = (const float*)d_in[12];
    const float* cattW       = (const float*)d_in[13];
    const float* cattb       = (const float*)d_in[14];
    const float* nodefW      = (const float*)d_in[15];
    const float* nodefb      = (const float*)d_in[16];
    const float* gk2_centers = (const float*)d_in[17];
    const float* gk2_prec    = (const float*)d_in[18];
    const float* emb2W       = (const float*)d_in[19];
    const float* emb2b       = (const float*)d_in[20];
    float* out = (float*)d_out;

    cudaFuncSetAttribute(gemm_epi_kernel,
                         cudaFuncAttributeMaxDynamicSharedMemorySize,
                         GE_SMEM_FLOATS * 4);

    prep_kernel<<<146, 256>>>(frame, opk, gk1_centers, gk1_prec,
                              gk2_centers, gk2_prec);
    knn_kernel<<<NROWS/8, 256>>>();
    stage1_kernel<<<NROWS/8, 256>>>(frame, attr, seq);
    gemm_epi_kernel<<<NROWS/64, 256, GE_SMEM_FLOATS*4>>>(
        opb, embW, embb, betaW, betab,
        sattW, sattb, cattW, cattb, nodefW, nodefb);
    stage2_kernel<<<NROWS/8, 256>>>(frame, seq, emb2W, emb2b, out);
}